// round 14
// baseline (speedup 1.0000x reference)
#include <cuda_runtime.h>
#include <cstdint>

#define NN 16
#define NSTEP 17
#define BMAX 131072
#define CTA_S 64
#define NT 256
#define MAXSLOT 12

// static scratch: feature-major [64][BMAX] activation buffers + transposed weights
__device__ float g_slot[MAXSLOT][64 * BMAX];
__device__ float g_wt[NSTEP][4096];          // [k][o]

struct Plan {
    int nslot;
    int encSlot, aggSlot;
    int srcSlot[NSTEP];
    int sumSlot[NSTEP];
    int outSlot[NSTEP];
    int accum[NSTEP];
    int act[NSTEP];
    int nPreds[NSTEP];
    unsigned char predSlot[NSTEP][NN];
};

// ---------------- helpers ----------------

__device__ __forceinline__ unsigned long long pk2(float x) {
    unsigned long long r; unsigned xi = __float_as_uint(x);
    asm("mov.b64 %0, {%1, %1};" : "=l"(r) : "r"(xi));
    return r;
}
__device__ __forceinline__ void upk2(unsigned long long v, float& lo, float& hi) {
    unsigned a, b;
    asm("mov.b64 {%0, %1}, %2;" : "=r"(a), "=r"(b) : "l"(v));
    lo = __uint_as_float(a); hi = __uint_as_float(b);
}
__device__ __forceinline__ void ffma2(unsigned long long& acc,
                                      unsigned long long a, unsigned long long b) {
    asm("fma.rn.f32x2 %0, %1, %2, %0;" : "+l"(acc) : "l"(a), "l"(b));
}
__device__ __forceinline__ float fast_tanh(float x) {
    float e = __expf(2.f * x);
    return 1.f - __fdividef(2.f, e + 1.f);
}
// GRAPH_ACTS = [tanh, elu, softplus, sin, gaussian]
__device__ __forceinline__ float actf(int id, float v) {
    switch (id) {
        case 0:  return fast_tanh(v);
        case 1:  return v > 0.f ? v : (__expf(v) - 1.f);
        case 2:  return fmaxf(v, 0.f) + __logf(1.f + __expf(-fabsf(v)));
        case 3:  return __sinf(v);
        default: return __expf(-0.5f * v * v);
    }
}

// ---------------- weight transpose kernel: g_wt[l][k*64+o] = W_l[o][k] ----------------

__global__ void wt_kernel(const float* __restrict__ W1, const float* __restrict__ gW) {
    int l = blockIdx.x;
    const float* src = (l == 0) ? W1 : gW + (l - 1) * 4096;
    float* dst = g_wt[l];
    for (int i = threadIdx.x; i < 4096; i += blockDim.x) {
        int o = i >> 6, k = i & 63;
        dst[k * 64 + o] = src[i];
    }
}

// ---------------- main kernel ----------------

__global__ void __launch_bounds__(NT, 4)
inr_kernel(const float* __restrict__ inp, const float* __restrict__ lats,
           const float* __restrict__ Wl, const float* __restrict__ bl,
           const float* __restrict__ Wx, const float* __restrict__ Wy,
           const float* __restrict__ Wr, const float* __restrict__ b1,
           const float* __restrict__ gB, const float* __restrict__ outW,
           const float* __restrict__ outb, const float* __restrict__ scale,
           float* __restrict__ out, Plan pl) {
    const int t  = threadIdx.x;
    const int sq = t & 15;                   // sample quad 0..15
    const int oq = t >> 4;                   // output quad 0..15
    const int sb = blockIdx.x * CTA_S;
    const int s0 = sb + sq * 4;              // this thread's 4 samples

    // ---- encode -> g_slot[encSlot]: thread (se = t&63, fg = t>>6) ----
    {
        float* enc = g_slot[pl.encSlot];
        const int se = t & 63, fg = t >> 6;
        int gs = sb + se;
        float xs = inp[gs * 3 + 0], ys = inp[gs * 3 + 1], rs = inp[gs * 3 + 2];
        const float4* lp = (const float4*)(lats + gs * 8);
        float4 l0 = lp[0], l1 = lp[1];
#pragma unroll
        for (int i = 0; i < 16; i++) {
            int o = fg * 16 + i;
            const float4* wlr = (const float4*)(Wl + o * 8);
            float4 w0 = wlr[0], w1 = wlr[1];
            float pre = __ldg(bl + o);
            pre = fmaf(l0.x, w0.x, pre); pre = fmaf(l0.y, w0.y, pre);
            pre = fmaf(l0.z, w0.z, pre); pre = fmaf(l0.w, w0.w, pre);
            pre = fmaf(l1.x, w1.x, pre); pre = fmaf(l1.y, w1.y, pre);
            pre = fmaf(l1.z, w1.z, pre); pre = fmaf(l1.w, w1.w, pre);
            float lv = fast_tanh(pre);
            float xv = fast_tanh(xs * __ldg(Wx + o));
            float yv; { float z = ys * __ldg(Wy + o); yv = fmaxf(z, 0.f) + __logf(1.f + __expf(-fabsf(z))); }
            float rv; { float z = rs * __ldg(Wr + o); rv = z > 0.f ? z : (__expf(z) - 1.f); }
            float u = xv + yv + rv + lv;
            enc[(size_t)o * BMAX + gs] = __expf(-0.5f * u * u);
        }
    }

    // ---- 17 layers ----
    for (int st = 0; st < NSTEP; st++) {
        __syncthreads();                       // previous layer's stores visible (same CTA)

        int ss = pl.srcSlot[st];
        if (ss < 0) {                          // multi-pred elementwise sum
            int np = pl.nPreds[st];
            float* dst = g_slot[pl.sumSlot[st]];
#pragma unroll
            for (int i = 0; i < 4; i++) {
                int q = t + i * NT;            // 0..1023 quads: 64 rows x 16 quads
                int off = (q >> 4) * BMAX + sb + (q & 15) * 4;
                float4 v = *(const float4*)(g_slot[pl.predSlot[st][0]] + off);
                for (int p = 1; p < np; p++) {
                    float4 u = *(const float4*)(g_slot[pl.predSlot[st][p]] + off);
                    v.x += u.x; v.y += u.y; v.z += u.z; v.w += u.w;
                }
                *(float4*)(dst + off) = v;
            }
            ss = pl.sumSlot[st];
            __syncthreads();
        }

        // ---- GEMM: thread = 4 samples x 4 outputs ----
        const float* src = g_slot[ss] + s0;
        const float* wt  = g_wt[st] + oq * 4;   // 4 outputs' weights per k
        unsigned long long acc[4][2];
#pragma unroll
        for (int op = 0; op < 4; op++) { acc[op][0] = 0; acc[op][1] = 0; }

#pragma unroll 8
        for (int k = 0; k < 64; k++) {
            ulonglong2 av = *(const ulonglong2*)(src + (size_t)k * BMAX);  // (s0,s1),(s2,s3)
            float4 wv = *(const float4*)(wt + k * 64);                     // w0..w3
            unsigned long long w0 = pk2(wv.x), w1 = pk2(wv.y);
            unsigned long long w2 = pk2(wv.z), w3 = pk2(wv.w);
            ffma2(acc[0][0], av.x, w0); ffma2(acc[0][1], av.y, w0);
            ffma2(acc[1][0], av.x, w1); ffma2(acc[1][1], av.y, w1);
            ffma2(acc[2][0], av.x, w2); ffma2(acc[2][1], av.y, w2);
            ffma2(acc[3][0], av.x, w3); ffma2(acc[3][1], av.y, w3);
        }

        // ---- epilogue: bias + activation + store ----
        const float* bias = (st == 0) ? b1 : gB + (st - 1) * 64;
        float4 bv = *(const float4*)(bias + oq * 4);
        float bb[4] = {bv.x, bv.y, bv.z, bv.w};
        int os = pl.outSlot[st];
        bool acm = pl.accum[st] != 0;
        int aid = pl.act[st];
        float* ob = g_slot[os];
#pragma unroll
        for (int op = 0; op < 4; op++) {
            float v0, v1, v2, v3;
            upk2(acc[op][0], v0, v1);
            upk2(acc[op][1], v2, v3);
            float4 ve;
            ve.x = actf(aid, v0 + bb[op]); ve.y = actf(aid, v1 + bb[op]);
            ve.z = actf(aid, v2 + bb[op]); ve.w = actf(aid, v3 + bb[op]);
            float* pe = ob + (size_t)(oq * 4 + op) * BMAX + s0;
            if (acm) {
                float4 c = *(const float4*)pe;
                ve.x += c.x; ve.y += c.y; ve.z += c.z; ve.w += c.w;
            }
            *(float4*)pe = ve;
        }
    }
    __syncthreads();

    // ---- head: sigmoid((agg @ outW.T + outb) * scale) ----
    if (t < CTA_S) {
        int gs = sb + t;
        const float* ag = g_slot[pl.aggSlot] + gs;
        float a0 = __ldg(outb + 0), a1 = __ldg(outb + 1), a2 = __ldg(outb + 2);
#pragma unroll 16
        for (int k = 0; k < 64; k++) {
            float a = ag[(size_t)k * BMAX];
            a0 = fmaf(a, __ldg(outW + k), a0);
            a1 = fmaf(a, __ldg(outW + 64 + k), a1);
            a2 = fmaf(a, __ldg(outW + 128 + k), a2);
        }
        float sc = __ldg(scale);
        out[gs * 3 + 0] = __fdividef(1.f, 1.f + __expf(-a0 * sc));
        out[gs * 3 + 1] = __fdividef(1.f, 1.f + __expf(-a1 * sc));
        out[gs * 3 + 2] = __fdividef(1.f, 1.f + __expf(-a2 * sc));
    }
}

// ---------------- host: graph replication + slot plan ----------------

namespace {

struct MT19937 {
    uint32_t mt[624];
    int mti;
    void seed(uint32_t sd) {
        mt[0] = sd;
        for (int i = 1; i < 624; i++)
            mt[i] = 1812433253u * (mt[i-1] ^ (mt[i-1] >> 30)) + (uint32_t)i;
        mti = 624;
    }
    uint32_t next32() {
        if (mti >= 624) {
            for (int i = 0; i < 624; i++) {
                uint32_t y = (mt[i] & 0x80000000u) | (mt[(i+1)%624] & 0x7fffffffu);
                uint32_t v = mt[(i+397)%624] ^ (y >> 1);
                if (y & 1u) v ^= 0x9908b0dfu;
                mt[i] = v;
            }
            mti = 0;
        }
        uint32_t y = mt[mti++];
        y ^= y >> 11; y ^= (y << 7) & 0x9d2c5680u;
        y ^= (y << 15) & 0xefc60000u; y ^= y >> 18;
        return y;
    }
    double rnd() {
        uint32_t a = next32() >> 5, b = next32() >> 6;
        return (a * 67108864.0 + b) / 9007199254740992.0;
    }
    uint32_t randint(uint32_t n) {
        uint32_t rng = n - 1;
        if (rng == 0) return 0;
        uint32_t mask = rng;
        mask |= mask >> 1; mask |= mask >> 2; mask |= mask >> 4;
        mask |= mask >> 8; mask |= mask >> 16;
        uint32_t v;
        do { v = next32() & mask; } while (v > rng);
        return v;
    }
};

void build_plan(Plan& P) {
    MT19937 rng; rng.seed(0u);
    const int n = NN;
    bool adj[NN][NN] = {};
    for (int i = 0; i < n; i++)
        for (int d = 1; d <= 2; d++) {
            int j = (i + d) % n;
            if (rng.rnd() < 0.75) j = (int)rng.randint((uint32_t)n);
            int a = i < j ? i : j, b = i < j ? j : i;
            if (a != b) adj[a][b] = true;
        }
    unsigned pm[NN] = {};
    for (int a = 0; a < n; a++)
        for (int b = 0; b < n; b++)
            if (adj[a][b]) pm[b] |= 1u << a;
    for (int j = 1; j < n; j++)
        if (!pm[j]) {
            uint32_t a = rng.randint((uint32_t)j);
            adj[a][j] = true;
            pm[j] |= 1u << a;
        }
    bool isSink[NN];
    for (int j = 0; j < n; j++) {
        bool hs = false;
        for (int b = 0; b < n; b++) if (adj[j][b]) hs = true;
        isSink[j] = !hs;
    }

    int uses[18] = {0};
    uses[17] = 1;
    for (int j = 0; j < n; j++) {
        if (pm[j] == 0) uses[16]++;
        else for (int i = 0; i < n; i++) if ((pm[j] >> i) & 1) uses[i]++;
    }
    int freeS[24], nFree = 0, ns = 0;
    auto alloc = [&]() { return nFree ? freeS[--nFree] : ns++; };
    auto release = [&](int sl) { freeS[nFree++] = sl; };
    int slotOf[18];

    P.aggSlot = -1;
    slotOf[17] = alloc();
    P.encSlot = slotOf[17];

    P.srcSlot[0] = slotOf[17]; P.sumSlot[0] = -1; P.nPreds[0] = 0;
    P.act[0] = 3; P.accum[0] = 0;
    slotOf[16] = alloc();
    P.outSlot[0] = slotOf[16];
    if (--uses[17] == 0) release(slotOf[17]);

    for (int j = 0; j < n; j++) {
        int st = j + 1;
        P.act[st] = j % 5;
        P.sumSlot[st] = -1; P.nPreds[st] = 0;
        int np = 0;
        for (int i = 0; i < n; i++) if ((pm[j] >> i) & 1) np++;

        int srcVal = -1;
        if (np == 0) {
            srcVal = 16;
            P.srcSlot[st] = slotOf[16];
        } else if (np == 1) {
            int p = 0; while (!((pm[j] >> p) & 1)) p++;
            srcVal = p;
            P.srcSlot[st] = slotOf[p];
        } else {
            P.srcSlot[st] = -1; P.nPreds[st] = np;
            int c = 0;
            for (int i = 0; i < n; i++)
                if ((pm[j] >> i) & 1) P.predSlot[st][c++] = (unsigned char)slotOf[i];
            for (int i = 0; i < n; i++)
                if ((pm[j] >> i) & 1) { if (--uses[i] == 0) release(slotOf[i]); }
            P.sumSlot[st] = alloc();
        }

        if (isSink[j]) {
            if (P.aggSlot < 0) { P.aggSlot = alloc(); P.accum[st] = 0; }
            else P.accum[st] = 1;
            P.outSlot[st] = P.aggSlot;
        } else {
            P.accum[st] = 0;
            slotOf[j] = alloc();
            P.outSlot[st] = slotOf[j];
        }

        if (np > 1) release(P.sumSlot[st]);
        else if (--uses[srcVal] == 0) release(slotOf[srcVal]);
    }
    P.nslot = ns;
}

}  // namespace

// ---------------- launch ----------------

extern "C" void kernel_launch(void* const* d_in, const int* in_sizes, int n_in,
                              void* d_out, int out_size) {
    (void)n_in; (void)out_size;
    Plan pl;
    build_plan(pl);

    const int B = in_sizes[0] / 3;
    const int ntiles = B / CTA_S;

    // stage transposed weights ([k][o]) for W1 + 16 graph nodes
    wt_kernel<<<NSTEP, 256>>>((const float*)d_in[7], (const float*)d_in[9]);

    inr_kernel<<<ntiles, NT>>>(
        (const float*)d_in[0],  (const float*)d_in[1],  (const float*)d_in[2],
        (const float*)d_in[3],  (const float*)d_in[4],  (const float*)d_in[5],
        (const float*)d_in[6],  (const float*)d_in[8],  (const float*)d_in[10],
        (const float*)d_in[11], (const float*)d_in[12], (const float*)d_in[13],
        (float*)d_out, pl);
}

// round 15
// speedup vs baseline: 1.2122x; 1.2122x over previous
#include <cuda_runtime.h>
#include <cstdint>

#define NN 16
#define NSTEP 17
#define BMAX 131072
#define CTA_S 128
#define NT 256
#define MAXSLOT 12

// static scratch: feature-major [64][BMAX] activation buffers + transposed weights
__device__ float g_slot[MAXSLOT][64 * BMAX];
__device__ float g_wt[NSTEP][4096];          // [k][o]

struct Plan {
    int nslot;
    int encSlot, aggSlot;
    int srcSlot[NSTEP];
    int outSlot[NSTEP];
    int accum[NSTEP];
    int act[NSTEP];
    int nPreds[NSTEP];
    unsigned char predSlot[NSTEP][NN];
};

// ---------------- helpers ----------------

__device__ __forceinline__ unsigned long long pk2(float x) {
    unsigned long long r; unsigned xi = __float_as_uint(x);
    asm("mov.b64 %0, {%1, %1};" : "=l"(r) : "r"(xi));
    return r;
}
__device__ __forceinline__ void upk2(unsigned long long v, float& lo, float& hi) {
    unsigned a, b;
    asm("mov.b64 {%0, %1}, %2;" : "=r"(a), "=r"(b) : "l"(v));
    lo = __uint_as_float(a); hi = __uint_as_float(b);
}
__device__ __forceinline__ void ffma2(unsigned long long& acc,
                                      unsigned long long a, unsigned long long b) {
    asm("fma.rn.f32x2 %0, %1, %2, %0;" : "+l"(acc) : "l"(a), "l"(b));
}
__device__ __forceinline__ float fast_tanh(float x) {
    float e = __expf(2.f * x);
    return 1.f - __fdividef(2.f, e + 1.f);
}
// GRAPH_ACTS = [tanh, elu, softplus, sin, gaussian]
__device__ __forceinline__ float actf(int id, float v) {
    switch (id) {
        case 0:  return fast_tanh(v);
        case 1:  return v > 0.f ? v : (__expf(v) - 1.f);
        case 2:  return fmaxf(v, 0.f) + __logf(1.f + __expf(-fabsf(v)));
        case 3:  return __sinf(v);
        default: return __expf(-0.5f * v * v);
    }
}
__device__ __forceinline__ void cp16(uint32_t smem_addr, const float* gptr) {
    asm volatile("cp.async.ca.shared.global [%0], [%1], 16;"
                 :: "r"(smem_addr), "l"(gptr) : "memory");
}

// ---------------- weight transpose kernel: g_wt[l][k*64+o] = W_l[o][k] ----------------

__global__ void wt_kernel(const float* __restrict__ W1, const float* __restrict__ gW) {
    int l = blockIdx.x;
    const float* src = (l == 0) ? W1 : gW + (l - 1) * 4096;
    float* dst = g_wt[l];
    for (int i = threadIdx.x; i < 4096; i += blockDim.x) {
        int o = i >> 6, k = i & 63;
        dst[k * 64 + o] = src[i];
    }
}

// ---------------- main kernel ----------------

__global__ void __launch_bounds__(NT, 3)
inr_kernel(const float* __restrict__ inp, const float* __restrict__ lats,
           const float* __restrict__ Wl, const float* __restrict__ bl,
           const float* __restrict__ Wx, const float* __restrict__ Wy,
           const float* __restrict__ Wr, const float* __restrict__ b1,
           const float* __restrict__ gB, const float* __restrict__ outW,
           const float* __restrict__ outb, const float* __restrict__ scale,
           float* __restrict__ out, Plan pl) {
    __shared__ float s_act[64 * CTA_S];       // 32 KB: current layer's input tile
    const int t    = threadIdx.x;
    const int og   = t >> 5;                 // warp owns outputs og*8..og*8+7
    const int lane = t & 31;
    const int sb   = blockIdx.x * CTA_S;
    const int s0   = sb + lane * 4;          // this lane's 4 global samples
    const int sl4  = lane * 4;               // local sample offset

    // ---- encode -> s_act (per-sample loop to limit live registers) ----
#pragma unroll 1
    for (int j = 0; j < 4; j++) {
        int gs = s0 + j;
        float xs = inp[gs * 3 + 0], ys = inp[gs * 3 + 1], rs = inp[gs * 3 + 2];
        const float4* lp = (const float4*)(lats + gs * 8);
        float4 l0 = lp[0], l1 = lp[1];
#pragma unroll
        for (int i = 0; i < 8; i++) {
            int o = og * 8 + i;
            const float4* wlr = (const float4*)(Wl + o * 8);
            float4 w0 = wlr[0], w1 = wlr[1];
            float pre = __ldg(bl + o);
            pre = fmaf(l0.x, w0.x, pre); pre = fmaf(l0.y, w0.y, pre);
            pre = fmaf(l0.z, w0.z, pre); pre = fmaf(l0.w, w0.w, pre);
            pre = fmaf(l1.x, w1.x, pre); pre = fmaf(l1.y, w1.y, pre);
            pre = fmaf(l1.z, w1.z, pre); pre = fmaf(l1.w, w1.w, pre);
            float lv = fast_tanh(pre);
            float xv = fast_tanh(xs * __ldg(Wx + o));
            float yv; { float z = ys * __ldg(Wy + o); yv = fmaxf(z, 0.f) + __logf(1.f + __expf(-fabsf(z))); }
            float rv; { float z = rs * __ldg(Wr + o); rv = z > 0.f ? z : (__expf(z) - 1.f); }
            float u = xv + yv + rv + lv;
            s_act[o * CTA_S + sl4 + j] = __expf(-0.5f * u * u);
        }
    }

    // ---- 17 layers ----
    for (int st = 0; st < NSTEP; st++) {
        __syncthreads();        // st==0: encode visible; else: prev gemm done reading
                                // s_act; prev global stores visible (intra-CTA)
        if (st > 0) {
            int ss = pl.srcSlot[st];
            if (ss < 0) {       // multi-pred: sum directly into smem
                int np = pl.nPreds[st];
                const float* p0 = g_slot[pl.predSlot[st][0]] + sb;
#pragma unroll
                for (int i = 0; i < 8; i++) {
                    int q = t + i * NT;                 // 0..2047 float4 chunks
                    int off = (q >> 5) * BMAX + (q & 31) * 4;
                    float4 v = *(const float4*)(p0 + off);
                    for (int p = 1; p < np; p++) {
                        float4 u = *(const float4*)(g_slot[pl.predSlot[st][p]] + sb + off);
                        v.x += u.x; v.y += u.y; v.z += u.z; v.w += u.w;
                    }
                    *(float4*)(s_act + q * 4) = v;
                }
            } else {            // single source: async bulk copy L2 -> smem
                const float* p0 = g_slot[ss] + sb;
                uint32_t sa = (uint32_t)__cvta_generic_to_shared(s_act);
#pragma unroll
                for (int i = 0; i < 8; i++) {
                    int q = t + i * NT;
                    int off = (q >> 5) * BMAX + (q & 31) * 4;
                    cp16(sa + (uint32_t)(q * 16), p0 + off);
                }
                asm volatile("cp.async.commit_group;" ::: "memory");
                asm volatile("cp.async.wait_group 0;" ::: "memory");
            }
            __syncthreads();
        }

        // ---- GEMM: warp = 8 outputs x 128 samples; thread = 4 samples x 8 outs ----
        const float* src = s_act + sl4;
        const float* wt  = g_wt[st] + og * 8;   // [k][o] packed pairs (uniform LDG)
        unsigned long long acc[4][4];
#pragma unroll
        for (int op = 0; op < 4; op++)
#pragma unroll
            for (int j = 0; j < 4; j++) acc[op][j] = 0;

#pragma unroll 8
        for (int k = 0; k < 64; k++) {
            float4 av = *(const float4*)(src + k * CTA_S);           // LDS.128
            ulonglong2 wA = *(const ulonglong2*)(wt + k * 64);       // (w0,w1),(w2,w3)
            ulonglong2 wB = *(const ulonglong2*)(wt + k * 64 + 4);   // (w4,w5),(w6,w7)
            unsigned long long a0 = pk2(av.x), a1 = pk2(av.y);
            unsigned long long a2 = pk2(av.z), a3 = pk2(av.w);
            ffma2(acc[0][0], a0, wA.x); ffma2(acc[0][1], a1, wA.x);
            ffma2(acc[0][2], a2, wA.x); ffma2(acc[0][3], a3, wA.x);
            ffma2(acc[1][0], a0, wA.y); ffma2(acc[1][1], a1, wA.y);
            ffma2(acc[1][2], a2, wA.y); ffma2(acc[1][3], a3, wA.y);
            ffma2(acc[2][0], a0, wB.x); ffma2(acc[2][1], a1, wB.x);
            ffma2(acc[2][2], a2, wB.x); ffma2(acc[2][3], a3, wB.x);
            ffma2(acc[3][0], a0, wB.y); ffma2(acc[3][1], a1, wB.y);
            ffma2(acc[3][2], a2, wB.y); ffma2(acc[3][3], a3, wB.y);
        }

        // ---- epilogue: bias + activation + store to global slot ----
        const float* bias = (st == 0) ? b1 : gB + (st - 1) * 64;
        int os = pl.outSlot[st];
        bool acm = pl.accum[st] != 0;
        int aid = pl.act[st];
        float* ob = g_slot[os];
#pragma unroll
        for (int op = 0; op < 4; op++) {
            float b0 = __ldg(bias + og * 8 + 2 * op);
            float b1v = __ldg(bias + og * 8 + 2 * op + 1);
            float e[4], o_[4];
#pragma unroll
            for (int j = 0; j < 4; j++) upk2(acc[op][j], e[j], o_[j]);
            float4 ve, vo;
            ve.x = actf(aid, e[0] + b0);  ve.y = actf(aid, e[1] + b0);
            ve.z = actf(aid, e[2] + b0);  ve.w = actf(aid, e[3] + b0);
            vo.x = actf(aid, o_[0] + b1v); vo.y = actf(aid, o_[1] + b1v);
            vo.z = actf(aid, o_[2] + b1v); vo.w = actf(aid, o_[3] + b1v);
            float* pe = ob + (og * 8 + 2 * op) * BMAX + s0;
            float* po = pe + BMAX;
            if (acm) {
                float4 ce = *(const float4*)pe, co = *(const float4*)po;
                ve.x += ce.x; ve.y += ce.y; ve.z += ce.z; ve.w += ce.w;
                vo.x += co.x; vo.y += co.y; vo.z += co.z; vo.w += co.w;
            }
            *(float4*)pe = ve;
            *(float4*)po = vo;
        }
    }
    __syncthreads();

    // ---- head: sigmoid((agg @ outW.T + outb) * scale) ----
    if (t < CTA_S) {
        int gs = sb + t;
        const float* ag = g_slot[pl.aggSlot] + gs;
        float a0 = __ldg(outb + 0), a1 = __ldg(outb + 1), a2 = __ldg(outb + 2);
#pragma unroll 16
        for (int k = 0; k < 64; k++) {
            float a = ag[(size_t)k * BMAX];
            a0 = fmaf(a, __ldg(outW + k), a0);
            a1 = fmaf(a, __ldg(outW + 64 + k), a1);
            a2 = fmaf(a, __ldg(outW + 128 + k), a2);
        }
        float sc = __ldg(scale);
        out[gs * 3 + 0] = __fdividef(1.f, 1.f + __expf(-a0 * sc));
        out[gs * 3 + 1] = __fdividef(1.f, 1.f + __expf(-a1 * sc));
        out[gs * 3 + 2] = __fdividef(1.f, 1.f + __expf(-a2 * sc));
    }
}

// ---------------- host: graph replication + slot plan ----------------

namespace {

struct MT19937 {
    uint32_t mt[624];
    int mti;
    void seed(uint32_t sd) {
        mt[0] = sd;
        for (int i = 1; i < 624; i++)
            mt[i] = 1812433253u * (mt[i-1] ^ (mt[i-1] >> 30)) + (uint32_t)i;
        mti = 624;
    }
    uint32_t next32() {
        if (mti >= 624) {
            for (int i = 0; i < 624; i++) {
                uint32_t y = (mt[i] & 0x80000000u) | (mt[(i+1)%624] & 0x7fffffffu);
                uint32_t v = mt[(i+397)%624] ^ (y >> 1);
                if (y & 1u) v ^= 0x9908b0dfu;
                mt[i] = v;
            }
            mti = 0;
        }
        uint32_t y = mt[mti++];
        y ^= y >> 11; y ^= (y << 7) & 0x9d2c5680u;
        y ^= (y << 15) & 0xefc60000u; y ^= y >> 18;
        return y;
    }
    double rnd() {
        uint32_t a = next32() >> 5, b = next32() >> 6;
        return (a * 67108864.0 + b) / 9007199254740992.0;
    }
    uint32_t randint(uint32_t n) {
        uint32_t rng = n - 1;
        if (rng == 0) return 0;
        uint32_t mask = rng;
        mask |= mask >> 1; mask |= mask >> 2; mask |= mask >> 4;
        mask |= mask >> 8; mask |= mask >> 16;
        uint32_t v;
        do { v = next32() & mask; } while (v > rng);
        return v;
    }
};

void build_plan(Plan& P) {
    MT19937 rng; rng.seed(0u);
    const int n = NN;
    bool adj[NN][NN] = {};
    for (int i = 0; i < n; i++)
        for (int d = 1; d <= 2; d++) {
            int j = (i + d) % n;
            if (rng.rnd() < 0.75) j = (int)rng.randint((uint32_t)n);
            int a = i < j ? i : j, b = i < j ? j : i;
            if (a != b) adj[a][b] = true;
        }
    unsigned pm[NN] = {};
    for (int a = 0; a < n; a++)
        for (int b = 0; b < n; b++)
            if (adj[a][b]) pm[b] |= 1u << a;
    for (int j = 1; j < n; j++)
        if (!pm[j]) {
            uint32_t a = rng.randint((uint32_t)j);
            adj[a][j] = true;
            pm[j] |= 1u << a;
        }
    bool isSink[NN];
    for (int j = 0; j < n; j++) {
        bool hs = false;
        for (int b = 0; b < n; b++) if (adj[j][b]) hs = true;
        isSink[j] = !hs;
    }

    // liveness slot allocation: values 0..15 nodes, 16 f, 17 enc
    int uses[18] = {0};
    uses[17] = 1;
    for (int j = 0; j < n; j++) {
        if (pm[j] == 0) uses[16]++;
        else for (int i = 0; i < n; i++) if ((pm[j] >> i) & 1) uses[i]++;
    }
    int freeS[24], nFree = 0, ns = 0;
    auto alloc = [&]() { return nFree ? freeS[--nFree] : ns++; };
    auto release = [&](int sl) { freeS[nFree++] = sl; };
    int slotOf[18];

    P.aggSlot = -1;
    slotOf[17] = alloc();
    P.encSlot = slotOf[17];

    P.srcSlot[0] = slotOf[17]; P.nPreds[0] = 0;
    P.act[0] = 3; P.accum[0] = 0;
    slotOf[16] = alloc();
    P.outSlot[0] = slotOf[16];
    if (--uses[17] == 0) release(slotOf[17]);

    for (int j = 0; j < n; j++) {
        int st = j + 1;
        P.act[st] = j % 5;
        P.nPreds[st] = 0;
        int np = 0;
        for (int i = 0; i < n; i++) if ((pm[j] >> i) & 1) np++;

        int srcVal = -1;
        if (np == 0) {
            srcVal = 16;
            P.srcSlot[st] = slotOf[16];
        } else if (np == 1) {
            int p = 0; while (!((pm[j] >> p) & 1)) p++;
            srcVal = p;
            P.srcSlot[st] = slotOf[p];
        } else {
            P.srcSlot[st] = -1; P.nPreds[st] = np;
            int c = 0;
            for (int i = 0; i < n; i++)
                if ((pm[j] >> i) & 1) P.predSlot[st][c++] = (unsigned char)slotOf[i];
            // preds consumed by the smem sum pass before the gemm writes
            for (int i = 0; i < n; i++)
                if ((pm[j] >> i) & 1) { if (--uses[i] == 0) release(slotOf[i]); }
        }

        if (isSink[j]) {
            if (P.aggSlot < 0) { P.aggSlot = alloc(); P.accum[st] = 0; }
            else P.accum[st] = 1;
            P.outSlot[st] = P.aggSlot;
        } else {
            P.accum[st] = 0;
            slotOf[j] = alloc();
            P.outSlot[st] = slotOf[j];
        }

        if (np <= 1) { if (--uses[srcVal] == 0) release(slotOf[srcVal]); }
    }
    P.nslot = ns;
}

}  // namespace

// ---------------- launch ----------------

extern "C" void kernel_launch(void* const* d_in, const int* in_sizes, int n_in,
                              void* d_out, int out_size) {
    (void)n_in; (void)out_size;
    Plan pl;
    build_plan(pl);

    const int B = in_sizes[0] / 3;
    const int ntiles = B / CTA_S;

    // stage transposed weights ([k][o]) for W1 + 16 graph nodes
    wt_kernel<<<NSTEP, 256>>>((const float*)d_in[7], (const float*)d_in[9]);

    inr_kernel<<<ntiles, NT>>>(
        (const float*)d_in[0],  (const float*)d_in[1],  (const float*)d_in[2],
        (const float*)d_in[3],  (const float*)d_in[4],  (const float*)d_in[5],
        (const float*)d_in[6],  (const float*)d_in[8],  (const float*)d_in[10],
        (const float*)d_in[11], (const float*)d_in[12], (const float*)d_in[13],
        (float*)d_out, pl);
}

// round 16
// speedup vs baseline: 2.5774x; 2.1262x over previous
#include <cuda_runtime.h>
#include <cstdint>

#define NN 16
#define NSTEP 17
#define BMAX 131072
#define NT 256
#define MAXSLOT 12

// thread-private fragment-ordered activation slots + fragment-packed split weights
__device__ float g_slot[MAXSLOT][BMAX * 64];
__device__ uint4 g_wt[NSTEP][1024];      // [(kk*8+nt)*32+lane] = {bh0,bh1,bl0,bl1}

struct Plan {
    int nslot;
    int srcSlot[NSTEP];     // step0 ignored (enc in regs); -1 => multi-pred sum in regs
    int outSlot[NSTEP];     // -1 => sink: accumulate in register agg
    int act[NSTEP];
    int nPreds[NSTEP];
    unsigned char predSlot[NSTEP][NN];
};

// ---------------- helpers ----------------

__device__ __forceinline__ float uf(uint32_t u) { return __uint_as_float(u); }
__device__ __forceinline__ uint32_t bf2(float lo, float hi) {  // pack: low16=lo
    uint32_t r;
    asm("cvt.rn.bf16x2.f32 %0, %1, %2;" : "=r"(r) : "f"(hi), "f"(lo));
    return r;
}
__device__ __forceinline__ float lo16(uint32_t h) { return uf(h << 16); }
__device__ __forceinline__ float hi16(uint32_t h) { return uf(h & 0xFFFF0000u); }

__device__ __forceinline__ void mma_bf16(float* c, uint32_t a0, uint32_t a1,
                                         uint32_t a2, uint32_t a3,
                                         uint32_t b0, uint32_t b1) {
    asm volatile(
        "mma.sync.aligned.m16n8k16.row.col.f32.bf16.bf16.f32 "
        "{%0,%1,%2,%3}, {%4,%5,%6,%7}, {%8,%9}, {%0,%1,%2,%3};"
        : "+f"(c[0]), "+f"(c[1]), "+f"(c[2]), "+f"(c[3])
        : "r"(a0), "r"(a1), "r"(a2), "r"(a3), "r"(b0), "r"(b1));
}

__device__ __forceinline__ float fast_tanh(float x) {
    float e = __expf(2.f * x);
    return 1.f - __fdividef(2.f, e + 1.f);
}
// GRAPH_ACTS = [tanh, elu, softplus, sin, gaussian]
__device__ __forceinline__ float actf(int id, float v) {
    switch (id) {
        case 0:  return fast_tanh(v);
        case 1:  return v > 0.f ? v : (__expf(v) - 1.f);
        case 2:  return fmaxf(v, 0.f) + __logf(1.f + __expf(-fabsf(v)));
        case 3:  return __sinf(v);
        default: return __expf(-0.5f * v * v);
    }
}

// ---------------- weight fragment kernel ----------------
// B col-major n8k16 fragment: b0 = {B[k0][n], B[k0+1][n]}, b1 = {B[k0+8][n], B[k0+9][n]}
// with n = nt*8 + (lane>>2), k0 = kk*16 + (lane&3)*2;  B[k][n] = W[n][k]

__global__ void wt_kernel(const float* __restrict__ W1, const float* __restrict__ gW) {
    int l = blockIdx.x;
    const float* src = (l == 0) ? W1 : gW + (l - 1) * 4096;
    for (int e = threadIdx.x; e < 1024; e += blockDim.x) {
        int lane = e & 31, nt = (e >> 5) & 7, kk = e >> 8;
        int g = lane >> 2, tid = lane & 3;
        int n = nt * 8 + g;
        int k0 = kk * 16 + tid * 2;
        float w00 = src[n * 64 + k0],     w01 = src[n * 64 + k0 + 1];
        float w10 = src[n * 64 + k0 + 8], w11 = src[n * 64 + k0 + 9];
        uint32_t h0 = bf2(w00, w01), h1 = bf2(w10, w11);
        uint32_t l0 = bf2(w00 - lo16(h0), w01 - hi16(h0));
        uint32_t l1 = bf2(w10 - lo16(h1), w11 - hi16(h1));
        g_wt[l][e] = make_uint4(h0, h1, l0, l1);
    }
}

// ---------------- main kernel (no smem, no barriers) ----------------

__global__ void __launch_bounds__(NT, 2)
inr_kernel(const float* __restrict__ inp, const float* __restrict__ lats,
           const float* __restrict__ Wl, const float* __restrict__ bl,
           const float* __restrict__ Wx, const float* __restrict__ Wy,
           const float* __restrict__ Wr, const float* __restrict__ b1,
           const float* __restrict__ gB, const float* __restrict__ outW,
           const float* __restrict__ outb, const float* __restrict__ scale,
           float* __restrict__ out, Plan pl) {
    const int t    = threadIdx.x;
    const int w    = t >> 5, lane = t & 31;
    const int g    = lane >> 2, tid = lane & 3;
    const int blk  = blockIdx.x;
    const int sA   = blk * 128 + w * 16 + g;      // fragment rows: sA, sA+8
    const int sB   = sA + 8;
    const int fragBase = blk * 8192 + (w * 8) * 128 + lane * 4;  // float offset (nt=0)

    float vsrc[32];   // current source, f32 frag order [nt*4 + c]

    // ---- encode -> vsrc (registers; never stored) ----
    {
        float xA = inp[sA*3+0], yA = inp[sA*3+1], rA = inp[sA*3+2];
        float xB = inp[sB*3+0], yB = inp[sB*3+1], rB = inp[sB*3+2];
        const float4* lpA = (const float4*)(lats + sA * 8);
        const float4* lpB = (const float4*)(lats + sB * 8);
        float4 lA0 = lpA[0], lA1 = lpA[1];
        float4 lB0 = lpB[0], lB1 = lpB[1];
#pragma unroll
        for (int nt = 0; nt < 8; nt++) {
#pragma unroll
            for (int c = 0; c < 2; c++) {
                int o = nt * 8 + tid * 2 + c;
                const float4* wlr = (const float4*)(Wl + o * 8);
                float4 w0 = wlr[0], w1 = wlr[1];
                float blo = __ldg(bl + o), wx = __ldg(Wx + o);
                float wy = __ldg(Wy + o), wr = __ldg(Wr + o);
                float preA = blo, preB = blo;
                preA = fmaf(lA0.x,w0.x,preA); preA = fmaf(lA0.y,w0.y,preA);
                preA = fmaf(lA0.z,w0.z,preA); preA = fmaf(lA0.w,w0.w,preA);
                preA = fmaf(lA1.x,w1.x,preA); preA = fmaf(lA1.y,w1.y,preA);
                preA = fmaf(lA1.z,w1.z,preA); preA = fmaf(lA1.w,w1.w,preA);
                preB = fmaf(lB0.x,w0.x,preB); preB = fmaf(lB0.y,w0.y,preB);
                preB = fmaf(lB0.z,w0.z,preB); preB = fmaf(lB0.w,w0.w,preB);
                preB = fmaf(lB1.x,w1.x,preB); preB = fmaf(lB1.y,w1.y,preB);
                preB = fmaf(lB1.z,w1.z,preB); preB = fmaf(lB1.w,w1.w,preB);
                float lvA = fast_tanh(preA), lvB = fast_tanh(preB);
                float xvA = fast_tanh(xA * wx), xvB = fast_tanh(xB * wx);
                float yvA, yvB, rvA, rvB;
                { float z = yA * wy; yvA = fmaxf(z,0.f) + __logf(1.f + __expf(-fabsf(z))); }
                { float z = yB * wy; yvB = fmaxf(z,0.f) + __logf(1.f + __expf(-fabsf(z))); }
                { float z = rA * wr; rvA = z > 0.f ? z : (__expf(z) - 1.f); }
                { float z = rB * wr; rvB = z > 0.f ? z : (__expf(z) - 1.f); }
                float uA = xvA + yvA + rvA + lvA;
                float uB = xvB + yvB + rvB + lvB;
                vsrc[nt*4 + c]     = __expf(-0.5f * uA * uA);
                vsrc[nt*4 + 2 + c] = __expf(-0.5f * uB * uB);
            }
        }
    }

    float agg[32];
#pragma unroll
    for (int i = 0; i < 32; i++) agg[i] = 0.f;

    // ---- 17 layers, fully warp-local ----
    for (int st = 0; st < NSTEP; st++) {
        if (st > 0) {
            int ss = pl.srcSlot[st];
            if (ss >= 0) {
                const float* p = g_slot[ss] + fragBase;
#pragma unroll
                for (int nt = 0; nt < 8; nt++) {
                    float4 v = *(const float4*)(p + nt * 128);
                    vsrc[nt*4+0] = v.x; vsrc[nt*4+1] = v.y;
                    vsrc[nt*4+2] = v.z; vsrc[nt*4+3] = v.w;
                }
            } else {
                int np = pl.nPreds[st];
#pragma unroll
                for (int i = 0; i < 32; i++) vsrc[i] = 0.f;
                for (int p = 0; p < np; p++) {
                    const float* pp = g_slot[pl.predSlot[st][p]] + fragBase;
#pragma unroll
                    for (int nt = 0; nt < 8; nt++) {
                        float4 v = *(const float4*)(pp + nt * 128);
                        vsrc[nt*4+0] += v.x; vsrc[nt*4+1] += v.y;
                        vsrc[nt*4+2] += v.z; vsrc[nt*4+3] += v.w;
                    }
                }
            }
        }

        // split fp32 -> bf16 hi/lo A-fragments
        uint32_t Ah[16], Al[16];
#pragma unroll
        for (int nt = 0; nt < 8; nt++) {
            float a0 = vsrc[nt*4+0], a1 = vsrc[nt*4+1];
            uint32_t h0 = bf2(a0, a1);
            Ah[nt*2]   = h0;
            Al[nt*2]   = bf2(a0 - lo16(h0), a1 - hi16(h0));
            float a2 = vsrc[nt*4+2], a3 = vsrc[nt*4+3];
            uint32_t h1 = bf2(a2, a3);
            Ah[nt*2+1] = h1;
            Al[nt*2+1] = bf2(a2 - lo16(h1), a3 - hi16(h1));
        }

        float acc[8][4];
#pragma unroll
        for (int nt = 0; nt < 8; nt++)
#pragma unroll
            for (int c = 0; c < 4; c++) acc[nt][c] = 0.f;

        const uint4* wt = g_wt[st] + lane;
#pragma unroll
        for (int kk = 0; kk < 4; kk++) {
            uint32_t a0h = Ah[4*kk],   a1h = Ah[4*kk+1];
            uint32_t a2h = Ah[4*kk+2], a3h = Ah[4*kk+3];
            uint32_t a0l = Al[4*kk],   a1l = Al[4*kk+1];
            uint32_t a2l = Al[4*kk+2], a3l = Al[4*kk+3];
#pragma unroll
            for (int nt = 0; nt < 8; nt++) {
                uint4 b = __ldg(wt + (kk * 8 + nt) * 32);
                mma_bf16(acc[nt], a0h, a1h, a2h, a3h, b.x, b.y);   // Ah*Bh
                mma_bf16(acc[nt], a0h, a1h, a2h, a3h, b.z, b.w);   // Ah*Bl
                mma_bf16(acc[nt], a0l, a1l, a2l, a3l, b.x, b.y);   // Al*Bh
            }
        }

        // epilogue
        const float* bias = (st == 0) ? b1 : gB + (st - 1) * 64;
        int aid = pl.act[st];
        int os  = pl.outSlot[st];
        float* ob = g_slot[(os >= 0) ? os : 0] + fragBase;
#pragma unroll
        for (int nt = 0; nt < 8; nt++) {
            float b0  = __ldg(bias + nt * 8 + tid * 2);
            float b1v = __ldg(bias + nt * 8 + tid * 2 + 1);
            float v0 = actf(aid, acc[nt][0] + b0);
            float v1 = actf(aid, acc[nt][1] + b1v);
            float v2 = actf(aid, acc[nt][2] + b0);
            float v3 = actf(aid, acc[nt][3] + b1v);
            if (os >= 0) {
                *(float4*)(ob + nt * 128) = make_float4(v0, v1, v2, v3);
            } else {
                agg[nt*4+0] += v0; agg[nt*4+1] += v1;
                agg[nt*4+2] += v2; agg[nt*4+3] += v3;
            }
        }
    }

    // ---- head: sigmoid((agg @ outW.T + outb) * scale) ----
    float sc = __ldg(scale);
#pragma unroll
    for (int ch = 0; ch < 3; ch++) {
        float pA = 0.f, pB = 0.f;
#pragma unroll
        for (int nt = 0; nt < 8; nt++) {
            int o = nt * 8 + tid * 2;
            float w0v = __ldg(outW + ch * 64 + o);
            float w1v = __ldg(outW + ch * 64 + o + 1);
            pA = fmaf(agg[nt*4+0], w0v, pA); pA = fmaf(agg[nt*4+1], w1v, pA);
            pB = fmaf(agg[nt*4+2], w0v, pB); pB = fmaf(agg[nt*4+3], w1v, pB);
        }
        pA += __shfl_xor_sync(0xFFFFFFFFu, pA, 1);
        pA += __shfl_xor_sync(0xFFFFFFFFu, pA, 2);
        pB += __shfl_xor_sync(0xFFFFFFFFu, pB, 1);
        pB += __shfl_xor_sync(0xFFFFFFFFu, pB, 2);
        if (tid == 0) {
            float ob_ = __ldg(outb + ch);
            float rA = (pA + ob_) * sc;
            float rB = (pB + ob_) * sc;
            out[sA * 3 + ch] = __fdividef(1.f, 1.f + __expf(-rA));
            out[sB * 3 + ch] = __fdividef(1.f, 1.f + __expf(-rB));
        }
    }
}

// ---------------- host: graph replication + slot plan ----------------

namespace {

struct MT19937 {
    uint32_t mt[624];
    int mti;
    void seed(uint32_t sd) {
        mt[0] = sd;
        for (int i = 1; i < 624; i++)
            mt[i] = 1812433253u * (mt[i-1] ^ (mt[i-1] >> 30)) + (uint32_t)i;
        mti = 624;
    }
    uint32_t next32() {
        if (mti >= 624) {
            for (int i = 0; i < 624; i++) {
                uint32_t y = (mt[i] & 0x80000000u) | (mt[(i+1)%624] & 0x7fffffffu);
                uint32_t v = mt[(i+397)%624] ^ (y >> 1);
                if (y & 1u) v ^= 0x9908b0dfu;
                mt[i] = v;
            }
            mti = 0;
        }
        uint32_t y = mt[mti++];
        y ^= y >> 11; y ^= (y << 7) & 0x9d2c5680u;
        y ^= (y << 15) & 0xefc60000u; y ^= y >> 18;
        return y;
    }
    double rnd() {
        uint32_t a = next32() >> 5, b = next32() >> 6;
        return (a * 67108864.0 + b) / 9007199254740992.0;
    }
    uint32_t randint(uint32_t n) {
        uint32_t rng = n - 1;
        if (rng == 0) return 0;
        uint32_t mask = rng;
        mask |= mask >> 1; mask |= mask >> 2; mask |= mask >> 4;
        mask |= mask >> 8; mask |= mask >> 16;
        uint32_t v;
        do { v = next32() & mask; } while (v > rng);
        return v;
    }
};

void build_plan(Plan& P) {
    MT19937 rng; rng.seed(0u);
    const int n = NN;
    bool adj[NN][NN] = {};
    for (int i = 0; i < n; i++)
        for (int d = 1; d <= 2; d++) {
            int j = (i + d) % n;
            if (rng.rnd() < 0.75) j = (int)rng.randint((uint32_t)n);
            int a = i < j ? i : j, b = i < j ? j : i;
            if (a != b) adj[a][b] = true;
        }
    unsigned pm[NN] = {};
    for (int a = 0; a < n; a++)
        for (int b = 0; b < n; b++)
            if (adj[a][b]) pm[b] |= 1u << a;
    for (int j = 1; j < n; j++)
        if (!pm[j]) {
            uint32_t a = rng.randint((uint32_t)j);
            adj[a][j] = true;
            pm[j] |= 1u << a;
        }
    bool isSink[NN];
    for (int j = 0; j < n; j++) {
        bool hs = false;
        for (int b = 0; b < n; b++) if (adj[j][b]) hs = true;
        isSink[j] = !hs;
    }

    // liveness slot allocation: values 0..15 nodes, 16 = f (enc lives in regs)
    int uses[17] = {0};
    for (int j = 0; j < n; j++) {
        if (pm[j] == 0) uses[16]++;
        else for (int i = 0; i < n; i++) if ((pm[j] >> i) & 1) uses[i]++;
    }
    int freeS[24], nFree = 0, ns = 0;
    auto alloc = [&]() { return nFree ? freeS[--nFree] : ns++; };
    auto release = [&](int sl) { freeS[nFree++] = sl; };
    int slotOf[17];

    // step 0: f = sin(enc @ W1.T + b1), enc in registers
    P.srcSlot[0] = -2; P.nPreds[0] = 0; P.act[0] = 3;
    slotOf[16] = alloc();
    P.outSlot[0] = slotOf[16];

    for (int j = 0; j < n; j++) {
        int st = j + 1;
        P.act[st] = j % 5;
        P.nPreds[st] = 0;
        int np = 0;
        for (int i = 0; i < n; i++) if ((pm[j] >> i) & 1) np++;

        if (np == 0) {
            P.srcSlot[st] = slotOf[16];
            if (--uses[16] == 0) release(slotOf[16]);
        } else if (np == 1) {
            int p = 0; while (!((pm[j] >> p) & 1)) p++;
            P.srcSlot[st] = slotOf[p];
            if (--uses[p] == 0) release(slotOf[p]);
        } else {
            P.srcSlot[st] = -1; P.nPreds[st] = np;
            int c = 0;
            for (int i = 0; i < n; i++)
                if ((pm[j] >> i) & 1) P.predSlot[st][c++] = (unsigned char)slotOf[i];
            for (int i = 0; i < n; i++)
                if ((pm[j] >> i) & 1) { if (--uses[i] == 0) release(slotOf[i]); }
        }
        // reads precede writes within each thread, so aliasing src/out is safe
        if (isSink[j]) {
            P.outSlot[st] = -1;               // register aggregation
        } else {
            slotOf[j] = alloc();
            P.outSlot[st] = slotOf[j];
        }
    }
    P.nslot = ns;
}

}  // namespace

// ---------------- launch ----------------

extern "C" void kernel_launch(void* const* d_in, const int* in_sizes, int n_in,
                              void* d_out, int out_size) {
    (void)n_in; (void)out_size;
    Plan pl;
    build_plan(pl);

    const int B = in_sizes[0] / 3;
    const int ntiles = B / 128;

    // stage split-bf16 fragment-packed weights for W1 + 16 graph nodes
    wt_kernel<<<NSTEP, 256>>>((const float*)d_in[7], (const float*)d_in[9]);

    inr_kernel<<<ntiles, NT>>>(
        (const float*)d_in[0],  (const float*)d_in[1],  (const float*)d_in[2],
        (const float*)d_in[3],  (const float*)d_in[4],  (const float*)d_in[5],
        (const float*)d_in[6],  (const float*)d_in[8],  (const float*)d_in[10],
        (const float*)d_in[11], (const float*)d_in[12], (const float*)d_in[13],
        (float*)d_out, pl);
}